// round 4
// baseline (speedup 1.0000x reference)
#include <cuda_runtime.h>
#include <cstddef>

// FusionAdjacency: Af = rownorm( sigmoid(g)*scatter(s) + (1-sigmoid(g))*scatter(t) )
//
// Plan (write the 256 MB output exactly ONCE, no global atomics on it):
//   1. init:      zero per-row edge counts + row sums (8192 each)
//   2. hist:      per-edge atomicAdd into count[r] and rowsum[r] (+= w*val)
//   3. scan:      single-block exclusive scan of counts -> offsets; cursor=offset;
//                 rowinv = (s==0) ? 1 : 1/s
//   4. bin:       scatter each edge into its row bucket as {col, w*val*rowinv[r]}
//   5. row write: one CTA per row: zero 32KB smem row, apply bucket edges with
//                 smem atomicAdd, stream the finished row out with float4 __stcs.

#define NN 8192
#define EMAX (2 * 262144)   // total edges across both adjacencies (upper bound)

__device__ int    g_count[NN];
__device__ int    g_offset[NN + 1];
__device__ int    g_cursor[NN];
__device__ float  g_rowsum[NN];      // becomes 1/rowsum after scan
__device__ float2 g_bucket[EMAX];    // {bitcast(col), contrib}

// ---------------------------------------------------------------- pass 1
__global__ void init_kernel() {
    int i = blockIdx.x * blockDim.x + threadIdx.x;
    if (i < NN) {
        g_count[i] = 0;
        g_rowsum[i] = 0.0f;
    }
}

// ---------------------------------------------------------------- pass 2
__global__ void hist_rowsum_kernel(const int* __restrict__ rows_s,
                                   const float* __restrict__ vals_s, int Es,
                                   const int* __restrict__ rows_t,
                                   const float* __restrict__ vals_t, int Et,
                                   const float* __restrict__ gamma) {
    const float g = gamma[0];
    const float alpha = 1.0f / (1.0f + expf(-g));
    const float beta = 1.0f - alpha;
    const int tid = blockIdx.x * blockDim.x + threadIdx.x;
    const int stride = gridDim.x * blockDim.x;
    for (int e = tid; e < Es; e += stride) {
        int r = rows_s[e];
        atomicAdd(&g_count[r], 1);
        atomicAdd(&g_rowsum[r], alpha * vals_s[e]);
    }
    for (int e = tid; e < Et; e += stride) {
        int r = rows_t[e];
        atomicAdd(&g_count[r], 1);
        atomicAdd(&g_rowsum[r], beta * vals_t[e]);
    }
}

// ---------------------------------------------------------------- pass 3
// Single block, 1024 threads, 8 rows each = 8192. Exclusive scan of counts.
__global__ void scan_kernel() {
    __shared__ int sdata[1024];
    const int t = threadIdx.x;
    const int base = t * 8;

    int loc[8];
    int run = 0;
#pragma unroll
    for (int i = 0; i < 8; i++) {
        loc[i] = run;
        run += g_count[base + i];
    }
    const int threadSum = run;
    sdata[t] = threadSum;
    __syncthreads();

    // Hillis–Steele inclusive scan over 1024 partials
    for (int d = 1; d < 1024; d <<= 1) {
        int v = (t >= d) ? sdata[t - d] : 0;
        __syncthreads();
        sdata[t] += v;
        __syncthreads();
    }
    const int excl = sdata[t] - threadSum;

#pragma unroll
    for (int i = 0; i < 8; i++) {
        int off = excl + loc[i];
        g_offset[base + i] = off;
        g_cursor[base + i] = off;
        float s = g_rowsum[base + i];
        g_rowsum[base + i] = (s == 0.0f) ? 1.0f : (1.0f / s);
    }
    if (t == 1023) g_offset[NN] = excl + threadSum;
}

// ---------------------------------------------------------------- pass 4
__global__ void bin_kernel(const int* __restrict__ rows_s,
                           const int* __restrict__ cols_s,
                           const float* __restrict__ vals_s, int Es,
                           const int* __restrict__ rows_t,
                           const int* __restrict__ cols_t,
                           const float* __restrict__ vals_t, int Et,
                           const float* __restrict__ gamma) {
    const float g = gamma[0];
    const float alpha = 1.0f / (1.0f + expf(-g));
    const float beta = 1.0f - alpha;
    const int tid = blockIdx.x * blockDim.x + threadIdx.x;
    const int stride = gridDim.x * blockDim.x;
    for (int e = tid; e < Es; e += stride) {
        int r = rows_s[e];
        int idx = atomicAdd(&g_cursor[r], 1);
        float contrib = alpha * vals_s[e] * g_rowsum[r];
        g_bucket[idx] = make_float2(__int_as_float(cols_s[e]), contrib);
    }
    for (int e = tid; e < Et; e += stride) {
        int r = rows_t[e];
        int idx = atomicAdd(&g_cursor[r], 1);
        float contrib = beta * vals_t[e] * g_rowsum[r];
        g_bucket[idx] = make_float2(__int_as_float(cols_t[e]), contrib);
    }
}

// ---------------------------------------------------------------- pass 5
// One CTA per row. Accumulate row in smem, stream out with non-atomic stores.
__global__ __launch_bounds__(256) void row_write_kernel(float* __restrict__ out) {
    __shared__ float srow[NN];   // 32 KB

    const int r = blockIdx.x;
    const int t = threadIdx.x;

    // zero the smem row (vectorized: 2048 float4 / 256 threads = 8 each)
    float4* srow4 = reinterpret_cast<float4*>(srow);
#pragma unroll
    for (int i = 0; i < 8; i++) {
        srow4[t + i * 256] = make_float4(0.f, 0.f, 0.f, 0.f);
    }
    __syncthreads();

    // apply this row's edges (avg ~64 per row)
    const int beg = g_offset[r];
    const int end = g_offset[r + 1];
    for (int i = beg + t; i < end; i += 256) {
        float2 e = g_bucket[i];
        int c = __float_as_int(e.x);
        atomicAdd(&srow[c], e.y);
    }
    __syncthreads();

    // stream the finished row to global with streaming-hint float4 stores
    float4* out4 = reinterpret_cast<float4*>(out + (size_t)r * NN);
#pragma unroll
    for (int i = 0; i < 8; i++) {
        __stcs(&out4[t + i * 256], srow4[t + i * 256]);
    }
}

// ---------------------------------------------------------------- launch
extern "C" void kernel_launch(void* const* d_in, const int* in_sizes, int n_in,
                              void* d_out, int out_size) {
    const int*   rows_s = (const int*)d_in[0];
    const int*   cols_s = (const int*)d_in[1];
    const float* vals_s = (const float*)d_in[2];
    const int*   rows_t = (const int*)d_in[3];
    const int*   cols_t = (const int*)d_in[4];
    const float* vals_t = (const float*)d_in[5];
    const float* gamma  = (const float*)d_in[6];
    float* out = (float*)d_out;

    const int Es = in_sizes[0];
    const int Et = in_sizes[3];

    init_kernel<<<(NN + 255) / 256, 256>>>();

    hist_rowsum_kernel<<<1024, 256>>>(rows_s, vals_s, Es,
                                      rows_t, vals_t, Et, gamma);

    scan_kernel<<<1, 1024>>>();

    bin_kernel<<<1024, 256>>>(rows_s, cols_s, vals_s, Es,
                              rows_t, cols_t, vals_t, Et, gamma);

    row_write_kernel<<<NN, 256>>>(out);
}

// round 5
// speedup vs baseline: 1.3872x; 1.3872x over previous
#include <cuda_runtime.h>
#include <cstddef>

// FusionAdjacency: Af = rownorm( sigmoid(g)*scatter(s) + (1-sigmoid(g))*scatter(t) )
//
// R4 structure (back to R2's memset+scatter, with a custom streaming fill):
//   1. fill_kernel:    zero the 256MB output with float4 __stcs (replaces
//                      cudaMemsetAsync, which measured only ~5.1 TB/s);
//                      also zeros the 8192-entry row-sum scratch.
//   2. hist_kernel:    blended row sums via L2-resident atomics.
//   3. finalize:       rowsum -> guarded reciprocal.
//   4. scatter_kernel: per-edge RED.ADD of normalized contribution into the
//                      dense output (duplicates coalesce; normalization is
//                      linear so pre-scaling per edge is exact).

#define NN 8192

__device__ float g_row_inv[NN];   // row sums, then reciprocals

// ---------------------------------------------------------------- pass 1
// Full-chip streaming zero of the output + rowsum scratch.
__global__ __launch_bounds__(256) void fill_kernel(float4* __restrict__ out4,
                                                   int n4) {
    const int tid = blockIdx.x * blockDim.x + threadIdx.x;
    const int stride = gridDim.x * blockDim.x;
    const float4 z = make_float4(0.f, 0.f, 0.f, 0.f);
    // independent iterations -> deep store queue, streaming hint bypasses L1
    for (int i = tid; i < n4; i += stride) {
        __stcs(&out4[i], z);
    }
    if (tid < NN) g_row_inv[tid] = 0.0f;
}

// ---------------------------------------------------------------- pass 2
__global__ __launch_bounds__(256) void hist_kernel(
        const int* __restrict__ rows_s, const float* __restrict__ vals_s, int Es,
        const int* __restrict__ rows_t, const float* __restrict__ vals_t, int Et,
        const float* __restrict__ gamma) {
    const float g = gamma[0];
    const float alpha = 1.0f / (1.0f + expf(-g));
    const float beta = 1.0f - alpha;
    const int tid = blockIdx.x * blockDim.x + threadIdx.x;
    const int stride = gridDim.x * blockDim.x;
    // two independent chains per iteration for MLP
    for (int e = tid; e < Es; e += stride) {
        atomicAdd(&g_row_inv[__ldg(&rows_s[e])], alpha * __ldg(&vals_s[e]));
    }
    for (int e = tid; e < Et; e += stride) {
        atomicAdd(&g_row_inv[__ldg(&rows_t[e])], beta * __ldg(&vals_t[e]));
    }
}

// ---------------------------------------------------------------- pass 3
__global__ void finalize_kernel() {
    int i = blockIdx.x * blockDim.x + threadIdx.x;
    if (i < NN) {
        float s = g_row_inv[i];
        g_row_inv[i] = (s == 0.0f) ? 1.0f : (1.0f / s);
    }
}

// ---------------------------------------------------------------- pass 4
// One thread owns edge e of list s AND edge e of list t: two independent
// load->scale->RED chains, no loop-carried dependence.
__global__ __launch_bounds__(256) void scatter_kernel(
        const int* __restrict__ rows_s, const int* __restrict__ cols_s,
        const float* __restrict__ vals_s, int Es,
        const int* __restrict__ rows_t, const int* __restrict__ cols_t,
        const float* __restrict__ vals_t, int Et,
        const float* __restrict__ gamma, float* __restrict__ out) {
    const float g = gamma[0];
    const float alpha = 1.0f / (1.0f + expf(-g));
    const float beta = 1.0f - alpha;
    const int tid = blockIdx.x * blockDim.x + threadIdx.x;
    const int stride = gridDim.x * blockDim.x;

    const int n = (Es > Et) ? Es : Et;
    for (int e = tid; e < n; e += stride) {
        // ---- chain S (independent of chain T) ----
        int rs = 0, cs = 0;
        float vs = 0.0f;
        if (e < Es) {
            rs = __ldg(&rows_s[e]);
            cs = __ldg(&cols_s[e]);
            vs = __ldg(&vals_s[e]);
        }
        // ---- chain T ----
        int rt = 0, ct = 0;
        float vt = 0.0f;
        if (e < Et) {
            rt = __ldg(&rows_t[e]);
            ct = __ldg(&cols_t[e]);
            vt = __ldg(&vals_t[e]);
        }
        // rowinv loads (L2-hot) — issue both before either RED
        float invs = g_row_inv[rs];
        float invt = g_row_inv[rt];
        if (e < Es) {
            atomicAdd(&out[((size_t)rs << 13) + cs], alpha * vs * invs);
        }
        if (e < Et) {
            atomicAdd(&out[((size_t)rt << 13) + ct], beta * vt * invt);
        }
    }
}

// ---------------------------------------------------------------- launch
extern "C" void kernel_launch(void* const* d_in, const int* in_sizes, int n_in,
                              void* d_out, int out_size) {
    const int*   rows_s = (const int*)d_in[0];
    const int*   cols_s = (const int*)d_in[1];
    const float* vals_s = (const float*)d_in[2];
    const int*   rows_t = (const int*)d_in[3];
    const int*   cols_t = (const int*)d_in[4];
    const float* vals_t = (const float*)d_in[5];
    const float* gamma  = (const float*)d_in[6];
    float* out = (float*)d_out;

    const int Es = in_sizes[0];
    const int Et = in_sizes[3];
    const int n4 = out_size / 4;   // 16M float4

    // 1) streaming zero of output + rowsum scratch (one wave-friendly grid)
    fill_kernel<<<2368, 256>>>((float4*)out, n4);

    // 2) blended row sums
    hist_kernel<<<1024, 256>>>(rows_s, vals_s, Es, rows_t, vals_t, Et, gamma);

    // 3) guarded reciprocals
    finalize_kernel<<<(NN + 255) / 256, 256>>>();

    // 4) normalized scatter
    scatter_kernel<<<1024, 256>>>(rows_s, cols_s, vals_s, Es,
                                  rows_t, cols_t, vals_t, Et, gamma, out);
}